// round 1
// baseline (speedup 1.0000x reference)
#include <cuda_runtime.h>
#include <cuda_bf16.h>
#include <math.h>

#define B_  2
#define T_  2048
#define C_  1024
#define H_  16
#define HD_ 64
#define SCALE_ 0.125f   // 1/sqrt(64)

// Scratch: qkv activations [B,T,3C] and attention output [B,T,C]
__device__ float g_qkv[(size_t)B_ * T_ * 3 * C_];
__device__ float g_att[(size_t)B_ * T_ * C_];

// ---------------------------------------------------------------------------
// SGEMM: C = A[M,K] @ B[K,N], row-major fp32. 128x128x8, 256 thr, 8x8 microtile
// ---------------------------------------------------------------------------
#define GBM 128
#define GBN 128
#define GBK 8
#define GPITCH 132

__global__ __launch_bounds__(256) void sgemm_kernel(
    const float* __restrict__ A, const float* __restrict__ Bm,
    float* __restrict__ Cm, int M, int N, int K)
{
    __shared__ float As[GBK][GPITCH];   // A transposed: As[k][row]
    __shared__ float Bs[GBK][GPITCH];   // Bs[k][col]

    const int tid  = threadIdx.x;
    const int tx   = tid & 15;
    const int ty   = tid >> 4;
    const int row0 = blockIdx.y * GBM;
    const int col0 = blockIdx.x * GBN;

    // global-load mapping
    const int ar = tid >> 1;          // 0..127
    const int ac = (tid & 1) * 4;     // 0 or 4
    const int br = tid >> 5;          // 0..7
    const int bc = (tid & 31) * 4;    // 0..124

    const float* Ap = A  + (size_t)(row0 + ar) * K + ac;
    const float* Bp = Bm + (size_t)br * N + col0 + bc;

    float4 apre = *(const float4*)Ap;
    float4 bpre = *(const float4*)Bp;

    float acc[8][8];
    #pragma unroll
    for (int i = 0; i < 8; i++)
        #pragma unroll
        for (int j = 0; j < 8; j++) acc[i][j] = 0.f;

    for (int k0 = 0; k0 < K; k0 += GBK) {
        As[ac + 0][ar] = apre.x;
        As[ac + 1][ar] = apre.y;
        As[ac + 2][ar] = apre.z;
        As[ac + 3][ar] = apre.w;
        *(float4*)&Bs[br][bc] = bpre;
        __syncthreads();

        if (k0 + GBK < K) {
            apre = *(const float4*)(Ap + k0 + GBK);
            bpre = *(const float4*)(Bp + (size_t)(k0 + GBK) * N);
        }

        #pragma unroll
        for (int kk = 0; kk < GBK; kk++) {
            float af[8], bf[8];
            *(float4*)&af[0] = *(const float4*)&As[kk][ty * 8];
            *(float4*)&af[4] = *(const float4*)&As[kk][ty * 8 + 4];
            *(float4*)&bf[0] = *(const float4*)&Bs[kk][tx * 8];
            *(float4*)&bf[4] = *(const float4*)&Bs[kk][tx * 8 + 4];
            #pragma unroll
            for (int i = 0; i < 8; i++)
                #pragma unroll
                for (int j = 0; j < 8; j++)
                    acc[i][j] += af[i] * bf[j];
        }
        __syncthreads();
    }

    float* Cp = Cm + (size_t)(row0 + ty * 8) * N + col0 + tx * 8;
    #pragma unroll
    for (int i = 0; i < 8; i++) {
        *(float4*)(Cp + (size_t)i * N)     = *(float4*)&acc[i][0];
        *(float4*)(Cp + (size_t)i * N + 4) = *(float4*)&acc[i][4];
    }
}

// ---------------------------------------------------------------------------
// Flash attention with causal mask + E8 rank-1 geometric bias
// Block: (b,h, 64-row q tile), 256 threads as 16(ty: q-rows) x 16(tx: cols)
// Each thread: 4x4 score block, 4x4 output block. Online softmax.
// ---------------------------------------------------------------------------
#define APITCH 68   // pitch for d-major Q/K tiles and P (conflict-free)

__global__ __launch_bounds__(256) void attn_kernel(
    const float* __restrict__ qkv, const float* __restrict__ head_scales,
    const float* __restrict__ head_dirs, float* __restrict__ out)
{
    extern __shared__ float sm[];
    float* Qt    = sm;                    // [64 d][APITCH r]
    float* KP    = Qt + HD_ * APITCH;     // Kt [64 d][APITCH c]; reused as P [64 r][APITCH c]
    float* Vs    = KP + HD_ * APITCH;     // [64 c][64 d]
    float* qproj = Vs + 64 * 64;          // [64]
    float* kproj = qproj + 64;            // [64]
    float* dirs  = kproj + 64;            // [8]

    const int tid = threadIdx.x;
    const int tx  = tid & 15;
    const int ty  = tid >> 4;
    const int bh  = blockIdx.y;
    const int b   = bh >> 4;     // H_ = 16
    const int h   = bh & 15;
    const int qi  = blockIdx.x;
    const int q0  = qi * 64;

    const float hs = head_scales[h];
    if (tid < 8) dirs[tid] = head_dirs[h * 8 + tid];

    // ---- load Q tile (transposed, d-major) ----
    {
        const int r  = tid >> 2;
        const int d0 = (tid & 3) * 16;
        const float* qrow = qkv + ((size_t)(b * T_ + q0 + r) * (3 * C_)) + h * HD_;
        #pragma unroll
        for (int dd = 0; dd < 16; dd += 4) {
            float4 v4 = *(const float4*)(qrow + d0 + dd);
            Qt[(d0 + dd + 0) * APITCH + r] = v4.x;
            Qt[(d0 + dd + 1) * APITCH + r] = v4.y;
            Qt[(d0 + dd + 2) * APITCH + r] = v4.z;
            Qt[(d0 + dd + 3) * APITCH + r] = v4.w;
        }
    }
    __syncthreads();
    if (tid < 64) {
        float s = 0.f;
        #pragma unroll
        for (int d = 0; d < 8; d++) s += Qt[d * APITCH + tid] * dirs[d];
        qproj[tid] = s;
    }

    float m_run[4] = {-INFINITY, -INFINITY, -INFINITY, -INFINITY};
    float l_run[4] = {0.f, 0.f, 0.f, 0.f};
    float oacc[4][4];
    #pragma unroll
    for (int i = 0; i < 4; i++)
        #pragma unroll
        for (int j = 0; j < 4; j++) oacc[i][j] = 0.f;

    for (int kt = 0; kt <= qi; kt++) {
        const int k0 = kt * 64;
        __syncthreads();   // prev iter done with KP/Vs; qproj visible on first iter

        // ---- load K (transposed) + V (row-major) ----
        {
            const int r  = tid >> 2;
            const int d0 = (tid & 3) * 16;
            const float* krow = qkv + ((size_t)(b * T_ + k0 + r) * (3 * C_)) + C_ + h * HD_;
            const float* vrow = krow + C_;
            #pragma unroll
            for (int dd = 0; dd < 16; dd += 4) {
                float4 kv = *(const float4*)(krow + d0 + dd);
                KP[(d0 + dd + 0) * APITCH + r] = kv.x;
                KP[(d0 + dd + 1) * APITCH + r] = kv.y;
                KP[(d0 + dd + 2) * APITCH + r] = kv.z;
                KP[(d0 + dd + 3) * APITCH + r] = kv.w;
                *(float4*)&Vs[r * 64 + d0 + dd] = *(const float4*)(vrow + d0 + dd);
            }
        }
        __syncthreads();
        if (tid < 64) {
            float s = 0.f;
            #pragma unroll
            for (int d = 0; d < 8; d++) s += KP[d * APITCH + tid] * dirs[d];
            kproj[tid] = s;
        }
        __syncthreads();

        // ---- scores: S = Q K^T ----
        float s[4][4];
        #pragma unroll
        for (int i = 0; i < 4; i++)
            #pragma unroll
            for (int j = 0; j < 4; j++) s[i][j] = 0.f;

        #pragma unroll 8
        for (int d = 0; d < HD_; d++) {
            float qf[4], kf[4];
            *(float4*)qf = *(const float4*)&Qt[d * APITCH + ty * 4];
            *(float4*)kf = *(const float4*)&KP[d * APITCH + tx * 4];
            #pragma unroll
            for (int i = 0; i < 4; i++)
                #pragma unroll
                for (int j = 0; j < 4; j++)
                    s[i][j] += qf[i] * kf[j];
        }

        // ---- scale + E8 bias + causal mask ----
        float qp[4], kp4[4];
        *(float4*)qp  = *(const float4*)&qproj[ty * 4];
        *(float4*)kp4 = *(const float4*)&kproj[tx * 4];
        const bool diag = (kt == qi);
        #pragma unroll
        for (int i = 0; i < 4; i++) {
            const int qrow = q0 + ty * 4 + i;
            #pragma unroll
            for (int j = 0; j < 4; j++) {
                float v = s[i][j] * SCALE_ + hs * qp[i] * kp4[j];
                if (diag && (k0 + tx * 4 + j > qrow)) v = -INFINITY;
                s[i][j] = v;
            }
        }

        // ---- online softmax ----
        float mx[4];
        #pragma unroll
        for (int i = 0; i < 4; i++)
            mx[i] = fmaxf(fmaxf(s[i][0], s[i][1]), fmaxf(s[i][2], s[i][3]));
        #pragma unroll
        for (int msk = 1; msk < 16; msk <<= 1) {
            #pragma unroll
            for (int i = 0; i < 4; i++)
                mx[i] = fmaxf(mx[i], __shfl_xor_sync(0xffffffffu, mx[i], msk));
        }
        float alpha[4];
        #pragma unroll
        for (int i = 0; i < 4; i++) {
            float mn = fmaxf(m_run[i], mx[i]);
            alpha[i] = __expf(m_run[i] - mn);
            m_run[i] = mn;
        }
        float rs[4];
        #pragma unroll
        for (int i = 0; i < 4; i++) {
            float r = 0.f;
            #pragma unroll
            for (int j = 0; j < 4; j++) {
                s[i][j] = __expf(s[i][j] - m_run[i]);
                r += s[i][j];
            }
            rs[i] = r;
        }
        #pragma unroll
        for (int msk = 1; msk < 16; msk <<= 1) {
            #pragma unroll
            for (int i = 0; i < 4; i++)
                rs[i] += __shfl_xor_sync(0xffffffffu, rs[i], msk);
        }
        #pragma unroll
        for (int i = 0; i < 4; i++) {
            l_run[i] = l_run[i] * alpha[i] + rs[i];
            #pragma unroll
            for (int j = 0; j < 4; j++) oacc[i][j] *= alpha[i];
        }

        // ---- P into smem (reuse K buffer) ----
        __syncthreads();
        #pragma unroll
        for (int i = 0; i < 4; i++)
            *(float4*)&KP[(ty * 4 + i) * APITCH + tx * 4] = *(float4*)&s[i][0];
        __syncthreads();

        // ---- O += P @ V ----
        #pragma unroll 2
        for (int c4 = 0; c4 < 64; c4 += 4) {
            float pf[4][4];
            #pragma unroll
            for (int i = 0; i < 4; i++)
                *(float4*)pf[i] = *(const float4*)&KP[(ty * 4 + i) * APITCH + c4];
            #pragma unroll
            for (int cc = 0; cc < 4; cc++) {
                float vf[4];
                *(float4*)vf = *(const float4*)&Vs[(c4 + cc) * 64 + tx * 4];
                #pragma unroll
                for (int i = 0; i < 4; i++)
                    #pragma unroll
                    for (int j = 0; j < 4; j++)
                        oacc[i][j] += pf[i][cc] * vf[j];
            }
        }
    }

    // ---- epilogue: out[b, t, h*64 + d] = o / l ----
    #pragma unroll
    for (int i = 0; i < 4; i++) {
        const float inv = 1.f / l_run[i];
        float4 o;
        o.x = oacc[i][0] * inv;
        o.y = oacc[i][1] * inv;
        o.z = oacc[i][2] * inv;
        o.w = oacc[i][3] * inv;
        float* orow = out + (size_t)(b * T_ + q0 + ty * 4 + i) * C_ + h * HD_ + tx * 4;
        *(float4*)orow = o;
    }
}

// ---------------------------------------------------------------------------
extern "C" void kernel_launch(void* const* d_in, const int* in_sizes, int n_in,
                              void* d_out, int out_size)
{
    const float* x           = (const float*)d_in[0];  // [2,2048,1024]
    const float* w_qkv       = (const float*)d_in[1];  // [1024,3072]
    const float* w_out       = (const float*)d_in[2];  // [1024,1024]
    const float* head_scales = (const float*)d_in[3];  // [16]
    const float* head_dirs   = (const float*)d_in[4];  // [16,8]
    float*       out         = (float*)d_out;          // [2,2048,1024]

    float* qkv = nullptr;
    float* att = nullptr;
    cudaGetSymbolAddress((void**)&qkv, g_qkv);
    cudaGetSymbolAddress((void**)&att, g_att);

    const int ATT_SMEM = (2 * HD_ * APITCH + 64 * 64 + 64 + 64 + 8) * (int)sizeof(float);
    cudaFuncSetAttribute(attn_kernel, cudaFuncAttributeMaxDynamicSharedMemorySize, ATT_SMEM);

    // 1) qkv = x @ w_qkv        [4096,1024] x [1024,3072]
    {
        dim3 grid((3 * C_) / GBN, (B_ * T_) / GBM);
        sgemm_kernel<<<grid, 256>>>(x, w_qkv, qkv, B_ * T_, 3 * C_, C_);
    }
    // 2) flash attention with E8 bias -> att [B,T,C]
    {
        dim3 grid(T_ / 64, B_ * H_);
        attn_kernel<<<grid, 256, ATT_SMEM>>>(qkv, head_scales, head_dirs, att);
    }
    // 3) out = att @ w_out      [4096,1024] x [1024,1024]
    {
        dim3 grid(C_ / GBN, (B_ * T_) / GBM);
        sgemm_kernel<<<grid, 256>>>(att, w_out, out, B_ * T_, C_, C_);
    }
}

// round 2
// speedup vs baseline: 1.3999x; 1.3999x over previous
#include <cuda_runtime.h>
#include <cuda_bf16.h>
#include <math.h>
#include <stdint.h>

#define B_  2
#define T_  2048
#define C_  1024
#define H_  16
#define HD_ 64
#define SCALE_ 0.125f   // 1/sqrt(64)
#define BT_ (B_ * T_)   // 4096

// ---------------- scratch (no allocations allowed) ----------------
__device__ float g_qkv[(size_t)BT_ * 3 * C_];
__device__ float g_att[(size_t)BT_ * C_];
__device__ __nv_bfloat16 g_xh[(size_t)BT_ * C_];
__device__ __nv_bfloat16 g_xl[(size_t)BT_ * C_];
__device__ __nv_bfloat16 g_ah[(size_t)BT_ * C_];
__device__ __nv_bfloat16 g_al[(size_t)BT_ * C_];
__device__ __nv_bfloat16 g_wqh[(size_t)3 * C_ * C_];   // [3C][C] -> stored [N][K]
__device__ __nv_bfloat16 g_wql[(size_t)3 * C_ * C_];
__device__ __nv_bfloat16 g_woh[(size_t)C_ * C_];
__device__ __nv_bfloat16 g_wol[(size_t)C_ * C_];

// ---------------------------------------------------------------------------
// helpers
// ---------------------------------------------------------------------------
__device__ __forceinline__ uint32_t smem_u32(const void* p) {
    return (uint32_t)__cvta_generic_to_shared(p);
}
__device__ __forceinline__ void ldsm_x4(uint32_t* r, uint32_t addr) {
    asm volatile("ldmatrix.sync.aligned.m8n8.x4.shared.b16 {%0,%1,%2,%3}, [%4];"
        : "=r"(r[0]), "=r"(r[1]), "=r"(r[2]), "=r"(r[3]) : "r"(addr));
}
__device__ __forceinline__ void ldsm_x2(uint32_t* r, uint32_t addr) {
    asm volatile("ldmatrix.sync.aligned.m8n8.x2.shared.b16 {%0,%1}, [%2];"
        : "=r"(r[0]), "=r"(r[1]) : "r"(addr));
}
__device__ __forceinline__ void mma_bf16(float* c, const uint32_t* a, const uint32_t* b) {
    asm volatile("mma.sync.aligned.m16n8k16.row.col.f32.bf16.bf16.f32 "
        "{%0,%1,%2,%3}, {%4,%5,%6,%7}, {%8,%9}, {%0,%1,%2,%3};"
        : "+f"(c[0]), "+f"(c[1]), "+f"(c[2]), "+f"(c[3])
        : "r"(a[0]), "r"(a[1]), "r"(a[2]), "r"(a[3]), "r"(b[0]), "r"(b[1]));
}

// ---------------------------------------------------------------------------
// split fp32 -> (bf16 hi, bf16 lo), same row-major layout
// ---------------------------------------------------------------------------
__global__ void split_kernel(const float* __restrict__ src,
                             __nv_bfloat16* __restrict__ hi,
                             __nv_bfloat16* __restrict__ lo, int n4)
{
    int i = blockIdx.x * blockDim.x + threadIdx.x;
    if (i >= n4) return;
    float4 v = ((const float4*)src)[i];
    __nv_bfloat16 hx = __float2bfloat16(v.x);
    __nv_bfloat16 hy = __float2bfloat16(v.y);
    __nv_bfloat16 hz = __float2bfloat16(v.z);
    __nv_bfloat16 hw = __float2bfloat16(v.w);
    __nv_bfloat162 h0, h1, l0, l1;
    h0.x = hx; h0.y = hy; h1.x = hz; h1.y = hw;
    l0.x = __float2bfloat16(v.x - __bfloat162float(hx));
    l0.y = __float2bfloat16(v.y - __bfloat162float(hy));
    l1.x = __float2bfloat16(v.z - __bfloat162float(hz));
    l1.y = __float2bfloat16(v.w - __bfloat162float(hw));
    ((__nv_bfloat162*)hi)[2 * i]     = h0;
    ((__nv_bfloat162*)hi)[2 * i + 1] = h1;
    ((__nv_bfloat162*)lo)[2 * i]     = l0;
    ((__nv_bfloat162*)lo)[2 * i + 1] = l1;
}

// ---------------------------------------------------------------------------
// split + transpose: src fp32 [K][N] -> hi/lo bf16 [N][K]
// ---------------------------------------------------------------------------
__global__ void split_transpose_kernel(const float* __restrict__ src,
                                       __nv_bfloat16* __restrict__ hi,
                                       __nv_bfloat16* __restrict__ lo,
                                       int K, int N)
{
    __shared__ float tile[32][33];
    const int n0 = blockIdx.x * 32, k0 = blockIdx.y * 32;
    const int tx = threadIdx.x, ty = threadIdx.y;
    for (int r = ty; r < 32; r += 8)
        tile[r][tx] = src[(size_t)(k0 + r) * N + n0 + tx];
    __syncthreads();
    for (int r = ty; r < 32; r += 8) {
        float v = tile[tx][r];             // src[k0+tx][n0+r]
        __nv_bfloat16 h = __float2bfloat16(v);
        hi[(size_t)(n0 + r) * K + k0 + tx] = h;
        lo[(size_t)(n0 + r) * K + k0 + tx] = __float2bfloat16(v - __bfloat162float(h));
    }
}

// ---------------------------------------------------------------------------
// bf16x3 tensor-core GEMM: C[M][N] = A[M][K] * B^T (B given [N][K] K-major)
// A,B pre-split into hi/lo bf16 planes. Block 128x128x32, 8 warps (64x32 tiles)
// ---------------------------------------------------------------------------
#define BM 128
#define BN 128
#define BK 32
#define SPITCH 40   // bf16 elems per smem row (80B) -> conflict-free ldmatrix

__global__ __launch_bounds__(256, 1) void gemm_bf16x3(
    const __nv_bfloat16* __restrict__ Ah, const __nv_bfloat16* __restrict__ Al,
    const __nv_bfloat16* __restrict__ Bh, const __nv_bfloat16* __restrict__ Bl,
    float* __restrict__ Cm, int M, int N, int K)
{
    __shared__ __nv_bfloat16 sAh[BM * SPITCH], sAl[BM * SPITCH];
    __shared__ __nv_bfloat16 sBh[BN * SPITCH], sBl[BN * SPITCH];

    const int tid  = threadIdx.x;
    const int lane = tid & 31, wid = tid >> 5;
    const int wm = (wid & 1) * 64;     // warp m offset within block
    const int wn = (wid >> 1) * 32;    // warp n offset within block

    const int row0 = blockIdx.y * BM;
    const int col0 = blockIdx.x * BN;

    // global load mapping: thread -> row gr (0..127), bf16 col gc (0 or 16),
    // two int4 (8 bf16 each) per plane
    const int gr = tid >> 1;
    const int gc = (tid & 1) * 16;
    const __nv_bfloat16* pAh = Ah + (size_t)(row0 + gr) * K + gc;
    const __nv_bfloat16* pAl = Al + (size_t)(row0 + gr) * K + gc;
    const __nv_bfloat16* pBh = Bh + (size_t)(col0 + gr) * K + gc;
    const __nv_bfloat16* pBl = Bl + (size_t)(col0 + gr) * K + gc;

    int4 rAh[2], rAl[2], rBh[2], rBl[2];
    rAh[0] = *(const int4*)pAh;        rAh[1] = *(const int4*)(pAh + 8);
    rAl[0] = *(const int4*)pAl;        rAl[1] = *(const int4*)(pAl + 8);
    rBh[0] = *(const int4*)pBh;        rBh[1] = *(const int4*)(pBh + 8);
    rBl[0] = *(const int4*)pBl;        rBl[1] = *(const int4*)(pBl + 8);

    float acc[4][4][4];
    #pragma unroll
    for (int i = 0; i < 4; i++)
        #pragma unroll
        for (int j = 0; j < 4; j++)
            #pragma unroll
            for (int k = 0; k < 4; k++) acc[i][j][k] = 0.f;

    // ldmatrix per-lane address components
    const int sub = lane >> 3, li = lane & 7;
    const int arow = (sub & 1) * 8 + li;   // + (wm + mf*16)
    const int acol = (sub >> 1) * 8;       // + ks
    const int brow = lane & 7;             // + (wn + nf*8)
    const int bcol = ((lane >> 3) & 1) * 8;

    const uint32_t baseAh = smem_u32(sAh), baseAl = smem_u32(sAl);
    const uint32_t baseBh = smem_u32(sBh), baseBl = smem_u32(sBl);

    for (int k0 = 0; k0 < K; k0 += BK) {
        *(int4*)&sAh[gr * SPITCH + gc]     = rAh[0];
        *(int4*)&sAh[gr * SPITCH + gc + 8] = rAh[1];
        *(int4*)&sAl[gr * SPITCH + gc]     = rAl[0];
        *(int4*)&sAl[gr * SPITCH + gc + 8] = rAl[1];
        *(int4*)&sBh[gr * SPITCH + gc]     = rBh[0];
        *(int4*)&sBh[gr * SPITCH + gc + 8] = rBh[1];
        *(int4*)&sBl[gr * SPITCH + gc]     = rBl[0];
        *(int4*)&sBl[gr * SPITCH + gc + 8] = rBl[1];
        __syncthreads();

        if (k0 + BK < K) {
            rAh[0] = *(const int4*)(pAh + k0 + BK); rAh[1] = *(const int4*)(pAh + k0 + BK + 8);
            rAl[0] = *(const int4*)(pAl + k0 + BK); rAl[1] = *(const int4*)(pAl + k0 + BK + 8);
            rBh[0] = *(const int4*)(pBh + k0 + BK); rBh[1] = *(const int4*)(pBh + k0 + BK + 8);
            rBl[0] = *(const int4*)(pBl + k0 + BK); rBl[1] = *(const int4*)(pBl + k0 + BK + 8);
        }

        #pragma unroll
        for (int ks = 0; ks < BK; ks += 16) {
            uint32_t fAh[4][4], fAl[4][4], fBh[4][2], fBl[4][2];
            #pragma unroll
            for (int mf = 0; mf < 4; mf++) {
                uint32_t off = (uint32_t)(((wm + mf * 16 + arow) * SPITCH + ks + acol) * 2);
                ldsm_x4(fAh[mf], baseAh + off);
                ldsm_x4(fAl[mf], baseAl + off);
            }
            #pragma unroll
            for (int nf = 0; nf < 4; nf++) {
                uint32_t off = (uint32_t)(((wn + nf * 8 + brow) * SPITCH + ks + bcol) * 2);
                ldsm_x2(fBh[nf], baseBh + off);
                ldsm_x2(fBl[nf], baseBl + off);
            }
            #pragma unroll
            for (int mf = 0; mf < 4; mf++)
                #pragma unroll
                for (int nf = 0; nf < 4; nf++) {
                    mma_bf16(acc[mf][nf], fAh[mf], fBh[nf]);
                    mma_bf16(acc[mf][nf], fAh[mf], fBl[nf]);
                    mma_bf16(acc[mf][nf], fAl[mf], fBh[nf]);
                }
        }
        __syncthreads();
    }

    // epilogue
    const int g = lane >> 2, t4 = lane & 3;
    #pragma unroll
    for (int mf = 0; mf < 4; mf++) {
        #pragma unroll
        for (int nf = 0; nf < 4; nf++) {
            const float* c = acc[mf][nf];
            const size_t r  = (size_t)(row0 + wm + mf * 16 + g);
            const size_t cc = (size_t)(col0 + wn + nf * 8 + 2 * t4);
            *(float2*)&Cm[r * N + cc]       = make_float2(c[0], c[1]);
            *(float2*)&Cm[(r + 8) * N + cc] = make_float2(c[2], c[3]);
        }
    }
}

// ---------------------------------------------------------------------------
// Flash attention with causal mask + E8 rank-1 geometric bias (unchanged R1)
// ---------------------------------------------------------------------------
#define APITCH 68

__global__ __launch_bounds__(256) void attn_kernel(
    const float* __restrict__ qkv, const float* __restrict__ head_scales,
    const float* __restrict__ head_dirs, float* __restrict__ out)
{
    extern __shared__ float sm[];
    float* Qt    = sm;
    float* KP    = Qt + HD_ * APITCH;
    float* Vs    = KP + HD_ * APITCH;
    float* qproj = Vs + 64 * 64;
    float* kproj = qproj + 64;
    float* dirs  = kproj + 64;

    const int tid = threadIdx.x;
    const int tx  = tid & 15;
    const int ty  = tid >> 4;
    const int bh  = blockIdx.y;
    const int b   = bh >> 4;
    const int h   = bh & 15;
    const int qi  = blockIdx.x;
    const int q0  = qi * 64;

    const float hs = head_scales[h];
    if (tid < 8) dirs[tid] = head_dirs[h * 8 + tid];

    {
        const int r  = tid >> 2;
        const int d0 = (tid & 3) * 16;
        const float* qrow = qkv + ((size_t)(b * T_ + q0 + r) * (3 * C_)) + h * HD_;
        #pragma unroll
        for (int dd = 0; dd < 16; dd += 4) {
            float4 v4 = *(const float4*)(qrow + d0 + dd);
            Qt[(d0 + dd + 0) * APITCH + r] = v4.x;
            Qt[(d0 + dd + 1) * APITCH + r] = v4.y;
            Qt[(d0 + dd + 2) * APITCH + r] = v4.z;
            Qt[(d0 + dd + 3) * APITCH + r] = v4.w;
        }
    }
    __syncthreads();
    if (tid < 64) {
        float s = 0.f;
        #pragma unroll
        for (int d = 0; d < 8; d++) s += Qt[d * APITCH + tid] * dirs[d];
        qproj[tid] = s;
    }

    float m_run[4] = {-INFINITY, -INFINITY, -INFINITY, -INFINITY};
    float l_run[4] = {0.f, 0.f, 0.f, 0.f};
    float oacc[4][4];
    #pragma unroll
    for (int i = 0; i < 4; i++)
        #pragma unroll
        for (int j = 0; j < 4; j++) oacc[i][j] = 0.f;

    for (int kt = 0; kt <= qi; kt++) {
        const int k0 = kt * 64;
        __syncthreads();

        {
            const int r  = tid >> 2;
            const int d0 = (tid & 3) * 16;
            const float* krow = qkv + ((size_t)(b * T_ + k0 + r) * (3 * C_)) + C_ + h * HD_;
            const float* vrow = krow + C_;
            #pragma unroll
            for (int dd = 0; dd < 16; dd += 4) {
                float4 kv = *(const float4*)(krow + d0 + dd);
                KP[(d0 + dd + 0) * APITCH + r] = kv.x;
                KP[(d0 + dd + 1) * APITCH + r] = kv.y;
                KP[(d0 + dd + 2) * APITCH + r] = kv.z;
                KP[(d0 + dd + 3) * APITCH + r] = kv.w;
                *(float4*)&Vs[r * 64 + d0 + dd] = *(const float4*)(vrow + d0 + dd);
            }
        }
        __syncthreads();
        if (tid < 64) {
            float s = 0.f;
            #pragma unroll
            for (int d = 0; d < 8; d++) s += KP[d * APITCH + tid] * dirs[d];
            kproj[tid] = s;
        }
        __syncthreads();

        float s[4][4];
        #pragma unroll
        for (int i = 0; i < 4; i++)
            #pragma unroll
            for (int j = 0; j < 4; j++) s[i][j] = 0.f;

        #pragma unroll 8
        for (int d = 0; d < HD_; d++) {
            float qf[4], kf[4];
            *(float4*)qf = *(const float4*)&Qt[d * APITCH + ty * 4];
            *(float4*)kf = *(const float4*)&KP[d * APITCH + tx * 4];
            #pragma unroll
            for (int i = 0; i < 4; i++)
                #pragma unroll
                for (int j = 0; j < 4; j++)
                    s[i][j] += qf[i] * kf[j];
        }

        float qp[4], kp4[4];
        *(float4*)qp  = *(const float4*)&qproj[ty * 4];
        *(float4*)kp4 = *(const float4*)&kproj[tx * 4];
        const bool diag = (kt == qi);
        #pragma unroll
        for (int i = 0; i < 4; i++) {
            const int qrow = q0 + ty * 4 + i;
            #pragma unroll
            for (int j = 0; j < 4; j++) {
                float v = s[i][j] * SCALE_ + hs * qp[i] * kp4[j];
                if (diag && (k0 + tx * 4 + j > qrow)) v = -INFINITY;
                s[i][j] = v;
            }
        }

        float mx[4];
        #pragma unroll
        for (int i = 0; i < 4; i++)
            mx[i] = fmaxf(fmaxf(s[i][0], s[i][1]), fmaxf(s[i][2], s[i][3]));
        #pragma unroll
        for (int msk = 1; msk < 16; msk <<= 1) {
            #pragma unroll
            for (int i = 0; i < 4; i++)
                mx[i] = fmaxf(mx[i], __shfl_xor_sync(0xffffffffu, mx[i], msk));
        }
        float alpha[4];
        #pragma unroll
        for (int i = 0; i < 4; i++) {
            float mn = fmaxf(m_run[i], mx[i]);
            alpha[i] = __expf(m_run[i] - mn);
            m_run[i] = mn;
        }
        float rs[4];
        #pragma unroll
        for (int i = 0; i < 4; i++) {
            float r = 0.f;
            #pragma unroll
            for (int j = 0; j < 4; j++) {
                s[i][j] = __expf(s[i][j] - m_run[i]);
                r += s[i][j];
            }
            rs[i] = r;
        }
        #pragma unroll
        for (int msk = 1; msk < 16; msk <<= 1) {
            #pragma unroll
            for (int i = 0; i < 4; i++)
                rs[i] += __shfl_xor_sync(0xffffffffu, rs[i], msk);
        }
        #pragma unroll
        for (int i = 0; i < 4; i++) {
            l_run[i] = l_run[i] * alpha[i] + rs[i];
            #pragma unroll
            for (int j = 0; j < 4; j++) oacc[i][j] *= alpha[i];
        }

        __syncthreads();
        #pragma unroll
        for (int i = 0; i < 4; i++)
            *(float4*)&KP[(ty * 4 + i) * APITCH + tx * 4] = *(float4*)&s[i][0];
        __syncthreads();

        #pragma unroll 2
        for (int c4 = 0; c4 < 64; c4 += 4) {
            float pf[4][4];
            #pragma unroll
            for (int i = 0; i < 4; i++)
                *(float4*)pf[i] = *(const float4*)&KP[(ty * 4 + i) * APITCH + c4];
            #pragma unroll
            for (int cc = 0; cc < 4; cc++) {
                float vf[4];
                *(float4*)vf = *(const float4*)&Vs[(c4 + cc) * 64 + tx * 4];
                #pragma unroll
                for (int i = 0; i < 4; i++)
                    #pragma unroll
                    for (int j = 0; j < 4; j++)
                        oacc[i][j] += pf[i][cc] * vf[j];
            }
        }
    }

    #pragma unroll
    for (int i = 0; i < 4; i++) {
        const float inv = 1.f / l_run[i];
        float4 o;
        o.x = oacc[i][0] * inv;
        o.y = oacc[i][1] * inv;
        o.z = oacc[i][2] * inv;
        o.w = oacc[i][3] * inv;
        float* orow = out + (size_t)(b * T_ + q0 + ty * 4 + i) * C_ + h * HD_ + tx * 4;
        *(float4*)orow = o;
    }
}

// ---------------------------------------------------------------------------
extern "C" void kernel_launch(void* const* d_in, const int* in_sizes, int n_in,
                              void* d_out, int out_size)
{
    const float* x           = (const float*)d_in[0];
    const float* w_qkv       = (const float*)d_in[1];
    const float* w_out       = (const float*)d_in[2];
    const float* head_scales = (const float*)d_in[3];
    const float* head_dirs   = (const float*)d_in[4];
    float*       out         = (float*)d_out;

    float *qkv, *att;
    __nv_bfloat16 *xh, *xl, *ah, *al, *wqh, *wql, *woh, *wol;
    cudaGetSymbolAddress((void**)&qkv, g_qkv);
    cudaGetSymbolAddress((void**)&att, g_att);
    cudaGetSymbolAddress((void**)&xh, g_xh);
    cudaGetSymbolAddress((void**)&xl, g_xl);
    cudaGetSymbolAddress((void**)&ah, g_ah);
    cudaGetSymbolAddress((void**)&al, g_al);
    cudaGetSymbolAddress((void**)&wqh, g_wqh);
    cudaGetSymbolAddress((void**)&wql, g_wql);
    cudaGetSymbolAddress((void**)&woh, g_woh);
    cudaGetSymbolAddress((void**)&wol, g_wol);

    const int ATT_SMEM = (2 * HD_ * APITCH + 64 * 64 + 64 + 64 + 8) * (int)sizeof(float);
    cudaFuncSetAttribute(attn_kernel, cudaFuncAttributeMaxDynamicSharedMemorySize, ATT_SMEM);

    // split inputs
    {
        int n4 = BT_ * C_ / 4;
        split_kernel<<<(n4 + 255) / 256, 256>>>(x, xh, xl, n4);
    }
    {
        dim3 grid(3 * C_ / 32, C_ / 32), blk(32, 8);
        split_transpose_kernel<<<grid, blk>>>(w_qkv, wqh, wql, C_, 3 * C_);
    }
    {
        dim3 grid(C_ / 32, C_ / 32), blk(32, 8);
        split_transpose_kernel<<<grid, blk>>>(w_out, woh, wol, C_, C_);
    }

    // 1) qkv = x @ w_qkv  (bf16x3 tensor core)
    {
        dim3 grid(3 * C_ / BN, BT_ / BM);
        gemm_bf16x3<<<grid, 256>>>(xh, xl, wqh, wql, qkv, BT_, 3 * C_, C_);
    }
    // 2) attention
    {
        dim3 grid(T_ / 64, B_ * H_);
        attn_kernel<<<grid, 256, ATT_SMEM>>>(qkv, head_scales, head_dirs, att);
    }
    // 3) split att, then out = att @ w_out
    {
        int n4 = BT_ * C_ / 4;
        split_kernel<<<(n4 + 255) / 256, 256>>>(att, ah, al, n4);
    }
    {
        dim3 grid(C_ / BN, BT_ / BM);
        gemm_bf16x3<<<grid, 256>>>(ah, al, woh, wol, out, BT_, C_, C_);
    }
}

// round 3
// speedup vs baseline: 2.3986x; 1.7134x over previous
#include <cuda_runtime.h>
#include <cuda_bf16.h>
#include <math.h>
#include <stdint.h>

#define B_  2
#define T_  2048
#define C_  1024
#define H_  16
#define HD_ 64
#define SCALE_ 0.125f
#define BT_ (B_ * T_)

typedef __nv_bfloat16 bf16;
typedef uint32_t u32;

// ---------------- scratch ----------------
__device__ bf16 g_xh[(size_t)BT_ * C_];
__device__ bf16 g_xl[(size_t)BT_ * C_];
__device__ bf16 g_qkvh[(size_t)BT_ * 3 * C_];
__device__ bf16 g_qkvl[(size_t)BT_ * 3 * C_];
__device__ bf16 g_ah[(size_t)BT_ * C_];
__device__ bf16 g_al[(size_t)BT_ * C_];
__device__ bf16 g_wqh[(size_t)3 * C_ * C_];
__device__ bf16 g_wql[(size_t)3 * C_ * C_];
__device__ bf16 g_woh[(size_t)C_ * C_];
__device__ bf16 g_wol[(size_t)C_ * C_];

// ---------------- helpers ----------------
__device__ __forceinline__ u32 smem_u32(const void* p) {
    return (u32)__cvta_generic_to_shared(p);
}
__device__ __forceinline__ void ldsm_x4(u32* r, u32 addr) {
    asm volatile("ldmatrix.sync.aligned.m8n8.x4.shared.b16 {%0,%1,%2,%3}, [%4];"
        : "=r"(r[0]), "=r"(r[1]), "=r"(r[2]), "=r"(r[3]) : "r"(addr));
}
__device__ __forceinline__ void ldsm_x2(u32* r, u32 addr) {
    asm volatile("ldmatrix.sync.aligned.m8n8.x2.shared.b16 {%0,%1}, [%2];"
        : "=r"(r[0]), "=r"(r[1]) : "r"(addr));
}
__device__ __forceinline__ void ldsm_x2t(u32* r, u32 addr) {
    asm volatile("ldmatrix.sync.aligned.m8n8.x2.trans.shared.b16 {%0,%1}, [%2];"
        : "=r"(r[0]), "=r"(r[1]) : "r"(addr));
}
__device__ __forceinline__ void mma_bf16(float* c, const u32* a, const u32* b) {
    asm volatile("mma.sync.aligned.m16n8k16.row.col.f32.bf16.bf16.f32 "
        "{%0,%1,%2,%3}, {%4,%5,%6,%7}, {%8,%9}, {%0,%1,%2,%3};"
        : "+f"(c[0]), "+f"(c[1]), "+f"(c[2]), "+f"(c[3])
        : "r"(a[0]), "r"(a[1]), "r"(a[2]), "r"(a[3]), "r"(b[0]), "r"(b[1]));
}
__device__ __forceinline__ u32 pack_bf16(float a, float b) {
    __nv_bfloat162 t;
    t.x = __float2bfloat16(a);
    t.y = __float2bfloat16(b);
    return *(u32*)&t;
}
__device__ __forceinline__ void split2(float a, float b, u32& hi, u32& lo) {
    __nv_bfloat16 ha = __float2bfloat16(a), hb = __float2bfloat16(b);
    __nv_bfloat162 Hh, Ll;
    Hh.x = ha; Hh.y = hb;
    Ll.x = __float2bfloat16(a - __bfloat162float(ha));
    Ll.y = __float2bfloat16(b - __bfloat162float(hb));
    hi = *(u32*)&Hh;
    lo = *(u32*)&Ll;
}

// ---------------------------------------------------------------------------
// split fp32 -> (bf16 hi, bf16 lo)
// ---------------------------------------------------------------------------
__global__ void split_kernel(const float* __restrict__ src,
                             bf16* __restrict__ hi, bf16* __restrict__ lo, int n4)
{
    int i = blockIdx.x * blockDim.x + threadIdx.x;
    if (i >= n4) return;
    float4 v = ((const float4*)src)[i];
    u32 h0, l0, h1, l1;
    split2(v.x, v.y, h0, l0);
    split2(v.z, v.w, h1, l1);
    ((u32*)hi)[2 * i]     = h0;
    ((u32*)hi)[2 * i + 1] = h1;
    ((u32*)lo)[2 * i]     = l0;
    ((u32*)lo)[2 * i + 1] = l1;
}

// split + transpose: src fp32 [K][N] -> hi/lo bf16 [N][K]
__global__ void split_transpose_kernel(const float* __restrict__ src,
                                       bf16* __restrict__ hi, bf16* __restrict__ lo,
                                       int K, int N)
{
    __shared__ float tile[32][33];
    const int n0 = blockIdx.x * 32, k0 = blockIdx.y * 32;
    const int tx = threadIdx.x, ty = threadIdx.y;
    for (int r = ty; r < 32; r += 8)
        tile[r][tx] = src[(size_t)(k0 + r) * N + n0 + tx];
    __syncthreads();
    for (int r = ty; r < 32; r += 8) {
        float v = tile[tx][r];
        __nv_bfloat16 h = __float2bfloat16(v);
        hi[(size_t)(n0 + r) * K + k0 + tx] = h;
        lo[(size_t)(n0 + r) * K + k0 + tx] = __float2bfloat16(v - __bfloat162float(h));
    }
}

// ---------------------------------------------------------------------------
// bf16x3 GEMM: C[M][N] = A[M][K] * B^T (B stored [N][K]); optional split output
// ---------------------------------------------------------------------------
#define BM 128
#define BN 128
#define BK 32
#define SPITCH 40

template<bool SPLIT>
__global__ __launch_bounds__(256, 1) void gemm_bf16x3(
    const bf16* __restrict__ Ah, const bf16* __restrict__ Al,
    const bf16* __restrict__ Bh, const bf16* __restrict__ Bl,
    float* __restrict__ Cm, bf16* __restrict__ Ch, bf16* __restrict__ Cl,
    int M, int N, int K)
{
    __shared__ bf16 sAh[BM * SPITCH], sAl[BM * SPITCH];
    __shared__ bf16 sBh[BN * SPITCH], sBl[BN * SPITCH];

    const int tid  = threadIdx.x;
    const int lane = tid & 31, wid = tid >> 5;
    const int wm = (wid & 1) * 64;
    const int wn = (wid >> 1) * 32;
    const int row0 = blockIdx.y * BM;
    const int col0 = blockIdx.x * BN;

    const int gr = tid >> 1;
    const int gc = (tid & 1) * 16;
    const bf16* pAh = Ah + (size_t)(row0 + gr) * K + gc;
    const bf16* pAl = Al + (size_t)(row0 + gr) * K + gc;
    const bf16* pBh = Bh + (size_t)(col0 + gr) * K + gc;
    const bf16* pBl = Bl + (size_t)(col0 + gr) * K + gc;

    int4 rAh[2], rAl[2], rBh[2], rBl[2];
    rAh[0] = *(const int4*)pAh;        rAh[1] = *(const int4*)(pAh + 8);
    rAl[0] = *(const int4*)pAl;        rAl[1] = *(const int4*)(pAl + 8);
    rBh[0] = *(const int4*)pBh;        rBh[1] = *(const int4*)(pBh + 8);
    rBl[0] = *(const int4*)pBl;        rBl[1] = *(const int4*)(pBl + 8);

    float acc[4][4][4];
    #pragma unroll
    for (int i = 0; i < 4; i++)
        #pragma unroll
        for (int j = 0; j < 4; j++)
            #pragma unroll
            for (int k = 0; k < 4; k++) acc[i][j][k] = 0.f;

    const int sub = lane >> 3, li = lane & 7;
    const int arow = (sub & 1) * 8 + li;
    const int acol = (sub >> 1) * 8;
    const int brow = lane & 7;
    const int bcol = ((lane >> 3) & 1) * 8;

    const u32 baseAh = smem_u32(sAh), baseAl = smem_u32(sAl);
    const u32 baseBh = smem_u32(sBh), baseBl = smem_u32(sBl);

    for (int k0 = 0; k0 < K; k0 += BK) {
        *(int4*)&sAh[gr * SPITCH + gc]     = rAh[0];
        *(int4*)&sAh[gr * SPITCH + gc + 8] = rAh[1];
        *(int4*)&sAl[gr * SPITCH + gc]     = rAl[0];
        *(int4*)&sAl[gr * SPITCH + gc + 8] = rAl[1];
        *(int4*)&sBh[gr * SPITCH + gc]     = rBh[0];
        *(int4*)&sBh[gr * SPITCH + gc + 8] = rBh[1];
        *(int4*)&sBl[gr * SPITCH + gc]     = rBl[0];
        *(int4*)&sBl[gr * SPITCH + gc + 8] = rBl[1];
        __syncthreads();

        if (k0 + BK < K) {
            rAh[0] = *(const int4*)(pAh + k0 + BK); rAh[1] = *(const int4*)(pAh + k0 + BK + 8);
            rAl[0] = *(const int4*)(pAl + k0 + BK); rAl[1] = *(const int4*)(pAl + k0 + BK + 8);
            rBh[0] = *(const int4*)(pBh + k0 + BK); rBh[1] = *(const int4*)(pBh + k0 + BK + 8);
            rBl[0] = *(const int4*)(pBl + k0 + BK); rBl[1] = *(const int4*)(pBl + k0 + BK + 8);
        }

        #pragma unroll
        for (int ks = 0; ks < BK; ks += 16) {
            u32 fAh[4][4], fAl[4][4], fBh[4][2], fBl[4][2];
            #pragma unroll
            for (int mf = 0; mf < 4; mf++) {
                u32 off = (u32)(((wm + mf * 16 + arow) * SPITCH + ks + acol) * 2);
                ldsm_x4(fAh[mf], baseAh + off);
                ldsm_x4(fAl[mf], baseAl + off);
            }
            #pragma unroll
            for (int nf = 0; nf < 4; nf++) {
                u32 off = (u32)(((wn + nf * 8 + brow) * SPITCH + ks + bcol) * 2);
                ldsm_x2(fBh[nf], baseBh + off);
                ldsm_x2(fBl[nf], baseBl + off);
            }
            #pragma unroll
            for (int mf = 0; mf < 4; mf++)
                #pragma unroll
                for (int nf = 0; nf < 4; nf++) {
                    mma_bf16(acc[mf][nf], fAh[mf], fBh[nf]);
                    mma_bf16(acc[mf][nf], fAh[mf], fBl[nf]);
                    mma_bf16(acc[mf][nf], fAl[mf], fBh[nf]);
                }
        }
        __syncthreads();
    }

    const int g = lane >> 2, t4 = lane & 3;
    #pragma unroll
    for (int mf = 0; mf < 4; mf++) {
        #pragma unroll
        for (int nf = 0; nf < 4; nf++) {
            const float* c = acc[mf][nf];
            const size_t r  = (size_t)(row0 + wm + mf * 16 + g);
            const size_t cc = (size_t)(col0 + wn + nf * 8 + 2 * t4);
            if (!SPLIT) {
                *(float2*)&Cm[r * N + cc]       = make_float2(c[0], c[1]);
                *(float2*)&Cm[(r + 8) * N + cc] = make_float2(c[2], c[3]);
            } else {
                u32 h01, l01, h23, l23;
                split2(c[0], c[1], h01, l01);
                split2(c[2], c[3], h23, l23);
                *(u32*)&Ch[r * N + cc]       = h01;
                *(u32*)&Cl[r * N + cc]       = l01;
                *(u32*)&Ch[(r + 8) * N + cc] = h23;
                *(u32*)&Cl[(r + 8) * N + cc] = l23;
            }
        }
    }
}

// ---------------------------------------------------------------------------
// Tensor-core flash attention with causal mask + E8 rank-1 bias (bf16x3)
// Block: (b,h, 128 q rows). 8 warps x 16 rows. 64-key tiles.
// ---------------------------------------------------------------------------
#define KPITCH 72   // bf16 pitch (144B): conflict-free ldmatrix

__global__ __launch_bounds__(256, 1) void attn_mma(
    const bf16* __restrict__ qkvh, const bf16* __restrict__ qkvl,
    const float* __restrict__ head_scales, const float* __restrict__ head_dirs,
    bf16* __restrict__ atth, bf16* __restrict__ attl)
{
    extern __shared__ bf16 dsm[];
    bf16* sQh = dsm;
    bf16* sQl = sQh + 128 * KPITCH;
    bf16* sKh = sQl + 128 * KPITCH;
    bf16* sKl = sKh + 64 * KPITCH;
    bf16* sVh = sKl + 64 * KPITCH;
    bf16* sVl = sVh + 64 * KPITCH;
    float* kproj = (float*)(sVl + 64 * KPITCH);
    float* dirs  = kproj + 64;

    const int tid  = threadIdx.x;
    const int lane = tid & 31, wid = tid >> 5;
    const int wm   = wid * 16;
    const int bh   = blockIdx.y;
    const int b    = bh >> 4;
    const int h    = bh & 15;
    const int qi   = (int)gridDim.x - 1 - (int)blockIdx.x;  // heavy tiles first
    const int q0   = qi * 128;

    const float hs = head_scales[h];
    if (tid < 8) dirs[tid] = head_dirs[h * 8 + tid];

    // ---- load Q tile (hi/lo) into smem ----
    #pragma unroll
    for (int i = tid; i < 128 * 8; i += 256) {
        const int row = i >> 3, seg = (i & 7) * 8;
        const size_t gb = (size_t)(b * T_ + q0 + row) * (3 * C_) + h * HD_ + seg;
        *(int4*)&sQh[row * KPITCH + seg] = *(const int4*)(qkvh + gb);
        *(int4*)&sQl[row * KPITCH + seg] = *(const int4*)(qkvl + gb);
    }
    __syncthreads();

    // ---- Q fragments (held in regs for the whole loop) ----
    const int sub = lane >> 3, li = lane & 7;
    const int arow = (sub & 1) * 8 + li;
    const int acol = (sub >> 1) * 8;
    const u32 baseQh = smem_u32(sQh), baseQl = smem_u32(sQl);
    u32 qfh[4][4], qfl[4][4];
    #pragma unroll
    for (int ks = 0; ks < 4; ks++) {
        u32 off = (u32)(((wm + arow) * KPITCH + ks * 16 + acol) * 2);
        ldsm_x4(qfh[ks], baseQh + off);
        ldsm_x4(qfl[ks], baseQl + off);
    }

    // ---- per-thread q projections (rows g, g+8) ----
    const int g = lane >> 2, t4 = lane & 3;
    float qp0 = 0.f, qp1 = 0.f;
    #pragma unroll
    for (int d = 0; d < 8; d++) {
        const int r0i = (wm + g) * KPITCH + d;
        qp0 += (__bfloat162float(sQh[r0i]) + __bfloat162float(sQl[r0i])) * dirs[d];
        const int r1i = (wm + g + 8) * KPITCH + d;
        qp1 += (__bfloat162float(sQh[r1i]) + __bfloat162float(sQl[r1i])) * dirs[d];
    }
    const float bq0 = hs * qp0, bq1 = hs * qp1;
    const int row_g0 = q0 + wm + g;       // global q row for c0,c1
    const int row_g1 = row_g0 + 8;        // for c2,c3

    float m0 = -INFINITY, m1 = -INFINITY, l0 = 0.f, l1 = 0.f;
    float o[8][4];
    #pragma unroll
    for (int j = 0; j < 8; j++)
        #pragma unroll
        for (int e = 0; e < 4; e++) o[j][e] = 0.f;

    const u32 baseKh = smem_u32(sKh), baseKl = smem_u32(sKl);
    const u32 baseVh = smem_u32(sVh), baseVl = smem_u32(sVl);
    const int brow = lane & 7;
    const int bcol = ((lane >> 3) & 1) * 8;
    const int vrow = lane & 15;

    const int ktmax = 2 * qi + 2;
    for (int kt = 0; kt < ktmax; kt++) {
        const int k0 = kt * 64;
        __syncthreads();   // previous tile's smem consumers done

        // ---- load K/V tile (hi/lo) ----
        #pragma unroll
        for (int i = tid; i < 64 * 8; i += 256) {
            const int row = i >> 3, seg = (i & 7) * 8;
            const size_t gb = (size_t)(b * T_ + k0 + row) * (3 * C_) + h * HD_ + seg;
            *(int4*)&sKh[row * KPITCH + seg] = *(const int4*)(qkvh + gb + C_);
            *(int4*)&sKl[row * KPITCH + seg] = *(const int4*)(qkvl + gb + C_);
            *(int4*)&sVh[row * KPITCH + seg] = *(const int4*)(qkvh + gb + 2 * C_);
            *(int4*)&sVl[row * KPITCH + seg] = *(const int4*)(qkvl + gb + 2 * C_);
        }
        __syncthreads();

        // ---- k projections ----
        if (tid < 64) {
            float s = 0.f;
            #pragma unroll
            for (int d = 0; d < 8; d++)
                s += (__bfloat162float(sKh[tid * KPITCH + d]) +
                      __bfloat162float(sKl[tid * KPITCH + d])) * dirs[d];
            kproj[tid] = s;
        }
        __syncthreads();

        // ---- S = Q K^T (bf16x3) ----
        float s[8][4];
        #pragma unroll
        for (int j = 0; j < 8; j++)
            #pragma unroll
            for (int e = 0; e < 4; e++) s[j][e] = 0.f;

        #pragma unroll
        for (int ks = 0; ks < 4; ks++) {
            #pragma unroll
            for (int j = 0; j < 8; j++) {
                u32 kh[2], kl[2];
                const u32 off = (u32)(((j * 8 + brow) * KPITCH + ks * 16 + bcol) * 2);
                ldsm_x2(kh, baseKh + off);
                ldsm_x2(kl, baseKl + off);
                mma_bf16(s[j], qfh[ks], kh);
                mma_bf16(s[j], qfh[ks], kl);
                mma_bf16(s[j], qfl[ks], kh);
            }
        }

        // ---- scale + bias + causal mask ----
        const bool need_mask = (kt >= 2 * qi);
        #pragma unroll
        for (int j = 0; j < 8; j++) {
            const float2 kp = *(const float2*)&kproj[j * 8 + 2 * t4];
            s[j][0] = s[j][0] * SCALE_ + bq0 * kp.x;
            s[j][1] = s[j][1] * SCALE_ + bq0 * kp.y;
            s[j][2] = s[j][2] * SCALE_ + bq1 * kp.x;
            s[j][3] = s[j][3] * SCALE_ + bq1 * kp.y;
            if (need_mask) {
                const int key0 = k0 + j * 8 + 2 * t4;
                if (key0 > row_g0)     s[j][0] = -INFINITY;
                if (key0 + 1 > row_g0) s[j][1] = -INFINITY;
                if (key0 > row_g1)     s[j][2] = -INFINITY;
                if (key0 + 1 > row_g1) s[j][3] = -INFINITY;
            }
        }

        // ---- online softmax ----
        float mx0 = s[0][0], mx1 = s[0][2];
        #pragma unroll
        for (int j = 0; j < 8; j++) {
            mx0 = fmaxf(mx0, fmaxf(s[j][0], s[j][1]));
            mx1 = fmaxf(mx1, fmaxf(s[j][2], s[j][3]));
        }
        mx0 = fmaxf(mx0, __shfl_xor_sync(0xffffffffu, mx0, 1));
        mx0 = fmaxf(mx0, __shfl_xor_sync(0xffffffffu, mx0, 2));
        mx1 = fmaxf(mx1, __shfl_xor_sync(0xffffffffu, mx1, 1));
        mx1 = fmaxf(mx1, __shfl_xor_sync(0xffffffffu, mx1, 2));

        const float mn0 = fmaxf(m0, mx0), mn1 = fmaxf(m1, mx1);
        const float a0 = __expf(m0 - mn0), a1 = __expf(m1 - mn1);
        m0 = mn0; m1 = mn1;

        float rs0 = 0.f, rs1 = 0.f;
        #pragma unroll
        for (int j = 0; j < 8; j++) {
            s[j][0] = __expf(s[j][0] - m0);
            s[j][1] = __expf(s[j][1] - m0);
            s[j][2] = __expf(s[j][2] - m1);
            s[j][3] = __expf(s[j][3] - m1);
            rs0 += s[j][0] + s[j][1];
            rs1 += s[j][2] + s[j][3];
        }
        rs0 += __shfl_xor_sync(0xffffffffu, rs0, 1);
        rs0 += __shfl_xor_sync(0xffffffffu, rs0, 2);
        rs1 += __shfl_xor_sync(0xffffffffu, rs1, 1);
        rs1 += __shfl_xor_sync(0xffffffffu, rs1, 2);
        l0 = l0 * a0 + rs0;
        l1 = l1 * a1 + rs1;

        #pragma unroll
        for (int j = 0; j < 8; j++) {
            o[j][0] *= a0; o[j][1] *= a0;
            o[j][2] *= a1; o[j][3] *= a1;
        }

        // ---- P fragments (hi/lo) from S accumulators ----
        u32 pah[4][4], pal[4][4];
        #pragma unroll
        for (int s2 = 0; s2 < 4; s2++) {
            split2(s[2 * s2][0],     s[2 * s2][1],     pah[s2][0], pal[s2][0]);
            split2(s[2 * s2][2],     s[2 * s2][3],     pah[s2][1], pal[s2][1]);
            split2(s[2 * s2 + 1][0], s[2 * s2 + 1][1], pah[s2][2], pal[s2][2]);
            split2(s[2 * s2 + 1][2], s[2 * s2 + 1][3], pah[s2][3], pal[s2][3]);
        }

        // ---- O += P V (bf16x3), V via ldmatrix.trans ----
        #pragma unroll
        for (int s2 = 0; s2 < 4; s2++) {
            #pragma unroll
            for (int j = 0; j < 8; j++) {
                u32 vh[2], vl[2];
                const u32 off = (u32)(((s2 * 16 + vrow) * KPITCH + j * 8) * 2);
                ldsm_x2t(vh, baseVh + off);
                ldsm_x2t(vl, baseVl + off);
                mma_bf16(o[j], pah[s2], vh);
                mma_bf16(o[j], pah[s2], vl);
                mma_bf16(o[j], pal[s2], vh);
            }
        }
    }

    // ---- epilogue: normalize, split, store hi/lo ----
    const float inv0 = 1.f / l0, inv1 = 1.f / l1;
    #pragma unroll
    for (int j = 0; j < 8; j++) {
        u32 h01, l01, h23, l23;
        split2(o[j][0] * inv0, o[j][1] * inv0, h01, l01);
        split2(o[j][2] * inv1, o[j][3] * inv1, h23, l23);
        const size_t r0o = (size_t)(b * T_ + row_g0) * C_ + h * HD_ + j * 8 + 2 * t4;
        const size_t r1o = (size_t)(b * T_ + row_g1) * C_ + h * HD_ + j * 8 + 2 * t4;
        *(u32*)&atth[r0o] = h01;
        *(u32*)&attl[r0o] = l01;
        *(u32*)&atth[r1o] = h23;
        *(u32*)&attl[r1o] = l23;
    }
}

// ---------------------------------------------------------------------------
extern "C" void kernel_launch(void* const* d_in, const int* in_sizes, int n_in,
                              void* d_out, int out_size)
{
    const float* x           = (const float*)d_in[0];
    const float* w_qkv       = (const float*)d_in[1];
    const float* w_out       = (const float*)d_in[2];
    const float* head_scales = (const float*)d_in[3];
    const float* head_dirs   = (const float*)d_in[4];
    float*       out         = (float*)d_out;

    bf16 *xh, *xl, *qkvh, *qkvl, *ah, *al, *wqh, *wql, *woh, *wol;
    cudaGetSymbolAddress((void**)&xh, g_xh);
    cudaGetSymbolAddress((void**)&xl, g_xl);
    cudaGetSymbolAddress((void**)&qkvh, g_qkvh);
    cudaGetSymbolAddress((void**)&qkvl, g_qkvl);
    cudaGetSymbolAddress((void**)&ah, g_ah);
    cudaGetSymbolAddress((void**)&al, g_al);
    cudaGetSymbolAddress((void**)&wqh, g_wqh);
    cudaGetSymbolAddress((void**)&wql, g_wql);
    cudaGetSymbolAddress((void**)&woh, g_woh);
    cudaGetSymbolAddress((void**)&wol, g_wol);

    const int ATT_SMEM = (128 * 2 + 64 * 4) * KPITCH * (int)sizeof(bf16)
                       + (64 + 8) * (int)sizeof(float);
    cudaFuncSetAttribute(attn_mma, cudaFuncAttributeMaxDynamicSharedMemorySize, ATT_SMEM);

    // splits
    {
        int n4 = BT_ * C_ / 4;
        split_kernel<<<(n4 + 255) / 256, 256>>>(x, xh, xl, n4);
    }
    {
        dim3 grid(3 * C_ / 32, C_ / 32), blk(32, 8);
        split_transpose_kernel<<<grid, blk>>>(w_qkv, wqh, wql, C_, 3 * C_);
    }
    {
        dim3 grid(C_ / 32, C_ / 32), blk(32, 8);
        split_transpose_kernel<<<grid, blk>>>(w_out, woh, wol, C_, C_);
    }

    // 1) qkv (split bf16 output)
    {
        dim3 grid(3 * C_ / BN, BT_ / BM);
        gemm_bf16x3<true><<<grid, 256>>>(xh, xl, wqh, wql,
                                         nullptr, qkvh, qkvl, BT_, 3 * C_, C_);
    }
    // 2) tensor-core attention (split bf16 output)
    {
        dim3 grid(T_ / 128, B_ * H_);
        attn_mma<<<grid, 256, ATT_SMEM>>>(qkvh, qkvl, head_scales, head_dirs, ah, al);
    }
    // 3) out = att @ w_out (fp32 output)
    {
        dim3 grid(C_ / BN, BT_ / BM);
        gemm_bf16x3<false><<<grid, 256>>>(ah, al, woh, wol,
                                          out, nullptr, nullptr, BT_, C_, C_);
    }
}